// round 9
// baseline (speedup 1.0000x reference)
#include <cuda_runtime.h>

#define Dn 32
#define Ln 65536

typedef unsigned long long u64;

// Dup'd weights in constant bank: cWd[((r*8+i)*5+w)*4+o] = pack(k, k)
__constant__ u64 cWd[640];

// Staging buffer written by the pack kernel, then memcpy'd into cWd.
__device__ u64 gPackD[640];

// ---- f32x2 packed helpers (Blackwell sm_100+) ----
__device__ __forceinline__ u64 pack2(float lo, float hi) {
    u64 r;
    asm("mov.b64 %0, {%1, %2};" : "=l"(r) : "f"(lo), "f"(hi));
    return r;
}
__device__ __forceinline__ u64 fma2(u64 a, u64 b, u64 c) {
    u64 d;
    asm("fma.rn.f32x2 %0, %1, %2, %3;" : "=l"(d) : "l"(a), "l"(b), "l"(c));
    return d;
}
__device__ __forceinline__ float2 unpack2(u64 v) {
    float2 f;
    asm("mov.b64 {%0, %1}, %2;" : "=f"(f.x), "=f"(f.y) : "l"(v));
    return f;
}

// Stage 1: dup-pack the 4 (4,8,5) kernels: one (k,k) u64 per (r,i,w,o).
__global__ void pack_weights_kernel(const float* __restrict__ k0,
                                    const float* __restrict__ k1,
                                    const float* __restrict__ k2,
                                    const float* __restrict__ k3)
{
    const int t = threadIdx.x;            // 0..639
    if (t >= 640) return;
    const int o = t & 3;
    const int w = (t >> 2) % 5;
    const int i = (t >> 2) / 5 % 8;
    const int r = t / 160;
    const float* ker = (r == 0) ? k0 : (r == 1) ? k1 : (r == 2) ? k2 : k3;
    const float v = ker[o * 40 + i * 5 + w];
    gPackD[t] = pack2(v, v);
}

// One thread: 4 consecutive output positions, all 4 out channels of one
// (batch, relation). Small per-thread tile -> acc = 8 u64 = 16 regs ->
// 5 CTAs/SM (40 warps) for latency hiding; the extra halo loads per
// output are L1/L2 hits, not DRAM.
__global__ __launch_bounds__(256, 5)
void conv4x8x5_kernel(const float* __restrict__ x, float* __restrict__ y)
{
    const int r = blockIdx.y;
    const int b = blockIdx.z;
    const u64* kr = cWd + r * 160;   // [(i*5+w)*4 + o]

    const int t  = threadIdx.x;
    const int l0 = (blockIdx.x * 256 + t) * 4;

    u64 acc[4][2];   // [o][q] : (out[l0+2q], out[l0+2q+1])
    #pragma unroll
    for (int o = 0; o < 4; o++) {
        acc[o][0] = 0ull;
        acc[o][1] = 0ull;
    }

    const float* xb = x + ((size_t)(b * Dn + 8 * r) * Ln) + l0;

    #pragma unroll 2
    for (int i = 0; i < 8; i++) {
        const float* xc = xb + (size_t)i * Ln;

        // Even-aligned pairs straight from memory:
        // E[j] = (x[l0+2j-2], x[l0+2j-1]), j = 0..3
        u64 E0 = (l0 > 0) ? *(const u64*)(xc - 2) : 0ull;
        ulonglong2 mid = *(const ulonglong2*)(xc);        // E1, E2
        u64 E1 = mid.x, E2 = mid.y;
        u64 E3 = (l0 < Ln - 4) ? *(const u64*)(xc + 4) : 0ull;

        // Odd-aligned pairs
        float2 f0 = unpack2(E0);
        float2 f1 = unpack2(E1);
        float2 f2 = unpack2(E2);
        float2 f3 = unpack2(E3);
        u64 O0 = pack2(f0.y, f1.x);
        u64 O1 = pack2(f1.y, f2.x);
        u64 O2 = pack2(f2.y, f3.x);

        const u64* wd = kr + i * 20;   // 5 taps x 4 out-ch, uniform const loads
        #pragma unroll
        for (int o = 0; o < 4; o++) {
            // q = 0: taps over E0,O0,E1,O1,E2
            u64 a0 = acc[o][0];
            a0 = fma2(wd[0 * 4 + o], E0, a0);
            a0 = fma2(wd[1 * 4 + o], O0, a0);
            a0 = fma2(wd[2 * 4 + o], E1, a0);
            a0 = fma2(wd[3 * 4 + o], O1, a0);
            a0 = fma2(wd[4 * 4 + o], E2, a0);
            acc[o][0] = a0;
            // q = 1: taps over E1,O1,E2,O2,E3
            u64 a1 = acc[o][1];
            a1 = fma2(wd[0 * 4 + o], E1, a1);
            a1 = fma2(wd[1 * 4 + o], O1, a1);
            a1 = fma2(wd[2 * 4 + o], E2, a1);
            a1 = fma2(wd[3 * 4 + o], O2, a1);
            a1 = fma2(wd[4 * 4 + o], E3, a1);
            acc[o][1] = a1;
        }
    }

    // acc[o][q] holds (out[l0+2q], out[l0+2q+1]) — one STG.128 per channel.
    float* yb = y + ((size_t)(b * 16 + 4 * r) * Ln) + l0;
    #pragma unroll
    for (int o = 0; o < 4; o++) {
        ulonglong2 s;
        s.x = acc[o][0];
        s.y = acc[o][1];
        *(ulonglong2*)(yb + (size_t)o * Ln) = s;
    }
}

extern "C" void kernel_launch(void* const* d_in, const int* in_sizes, int n_in,
                              void* d_out, int out_size)
{
    const float* x  = (const float*)d_in[0];
    const float* k0 = (const float*)d_in[1];
    const float* k1 = (const float*)d_in[2];
    const float* k2 = (const float*)d_in[3];
    const float* k3 = (const float*)d_in[4];
    float* y = (float*)d_out;

    // Stage 1: dup-pack weights (1 node).
    pack_weights_kernel<<<1, 640>>>(k0, k1, k2, k3);

    // Stage 2: single D2D memcpy into the constant bank (1 node).
    void* src = nullptr;
    cudaGetSymbolAddress(&src, gPackD);
    cudaMemcpyToSymbolAsync(cWd, src, 640 * sizeof(u64), 0,
                            cudaMemcpyDeviceToDevice, 0);

    // Stage 3: the conv. 4 positions/thread, 256 threads/block.
    dim3 grid(Ln / 1024, 4, 32);  // (pos tiles, relation, batch)
    dim3 block(256);
    conv4x8x5_kernel<<<grid, block>>>(x, y);
}

// round 10
// speedup vs baseline: 1.1307x; 1.1307x over previous
#include <cuda_runtime.h>

#define Dn 32
#define Ln 65536

typedef unsigned long long u64;

// Dup'd weights in constant bank: cWd[((r*8+i)*5+w)*4+o] = pack(k, k)
// Written directly by the pack kernel via its backing device address
// (cudaGetSymbolAddress on a __constant__ symbol) — saves a memcpy node.
__constant__ u64 cWd[640];

// ---- f32x2 packed helpers (Blackwell sm_100+) ----
__device__ __forceinline__ u64 pack2(float lo, float hi) {
    u64 r;
    asm("mov.b64 %0, {%1, %2};" : "=l"(r) : "f"(lo), "f"(hi));
    return r;
}
__device__ __forceinline__ u64 fma2(u64 a, u64 b, u64 c) {
    u64 d;
    asm("fma.rn.f32x2 %0, %1, %2, %3;" : "=l"(d) : "l"(a), "l"(b), "l"(c));
    return d;
}
__device__ __forceinline__ float2 unpack2(u64 v) {
    float2 f;
    asm("mov.b64 {%0, %1}, %2;" : "=f"(f.x), "=f"(f.y) : "l"(v));
    return f;
}

// Single staging node: dup-pack the 4 (4,8,5) kernels straight into the
// constant bank's backing store.
__global__ void pack_weights_kernel(const float* __restrict__ k0,
                                    const float* __restrict__ k1,
                                    const float* __restrict__ k2,
                                    const float* __restrict__ k3,
                                    u64* __restrict__ dst)
{
    const int t = threadIdx.x;            // 0..639
    if (t >= 640) return;
    const int o = t & 3;
    const int w = (t >> 2) % 5;
    const int i = (t >> 2) / 5 % 8;
    const int r = t / 160;
    const float* ker = (r == 0) ? k0 : (r == 1) ? k1 : (r == 2) ? k2 : k3;
    const float v = ker[o * 40 + i * 5 + w];
    dst[t] = pack2(v, v);
}

// One thread: 8 consecutive output positions, all 4 out channels of one
// (batch, relation). Accumulators are f32x2 over POSITION pairs; weight
// operand is a dup'd (k,k) u64 from the constant bank (uniform path);
// epilogue stores acc pairs directly as STG.128.
__global__ __launch_bounds__(256, 4)
void conv4x8x5_kernel(const float* __restrict__ x, float* __restrict__ y)
{
    const int r = blockIdx.y;
    const int b = blockIdx.z;
    const u64* kr = cWd + r * 160;   // [(i*5+w)*4 + o]

    const int t  = threadIdx.x;
    const int l0 = (blockIdx.x * 256 + t) * 8;

    u64 acc[4][4];   // [o][q] : (out[2q], out[2q+1])
    #pragma unroll
    for (int o = 0; o < 4; o++)
        #pragma unroll
        for (int q = 0; q < 4; q++)
            acc[o][q] = 0ull;

    const float* xb = x + ((size_t)(b * Dn + 8 * r) * Ln) + l0;

    #pragma unroll 2
    for (int i = 0; i < 8; i++) {
        const float* xc = xb + (size_t)i * Ln;

        // Even-aligned pairs straight from memory:
        // E[j] = (x[l0+2j-2], x[l0+2j-1]), j = 0..5
        u64 E[6];
        E[0] = (l0 > 0)      ? *(const u64*)(xc - 2) : 0ull;
        ulonglong2 mA = *(const ulonglong2*)(xc);       // E1, E2
        ulonglong2 mB = *(const ulonglong2*)(xc + 4);   // E3, E4
        E[1] = mA.x; E[2] = mA.y;
        E[3] = mB.x; E[4] = mB.y;
        E[5] = (l0 < Ln - 8) ? *(const u64*)(xc + 8) : 0ull;

        // Odd-aligned pairs: O[j] = (E[j].hi, E[j+1].lo)
        float2 f0 = unpack2(E[0]);
        float2 f1 = unpack2(E[1]);
        float2 f2 = unpack2(E[2]);
        float2 f3 = unpack2(E[3]);
        float2 f4 = unpack2(E[4]);
        float2 f5 = unpack2(E[5]);
        u64 O[5];
        O[0] = pack2(f0.y, f1.x);
        O[1] = pack2(f1.y, f2.x);
        O[2] = pack2(f2.y, f3.x);
        O[3] = pack2(f3.y, f4.x);
        O[4] = pack2(f4.y, f5.x);

        const u64* wd = kr + i * 20;   // 5 taps x 4 out-ch, uniform const loads
        #pragma unroll
        for (int q = 0; q < 4; q++) {
            #pragma unroll
            for (int o = 0; o < 4; o++) {
                u64 a = acc[o][q];
                a = fma2(wd[0 * 4 + o], E[q],     a);
                a = fma2(wd[1 * 4 + o], O[q],     a);
                a = fma2(wd[2 * 4 + o], E[q + 1], a);
                a = fma2(wd[3 * 4 + o], O[q + 1], a);
                a = fma2(wd[4 * 4 + o], E[q + 2], a);
                acc[o][q] = a;
            }
        }
    }

    // acc[o][q] already holds (out[2q], out[2q+1]) — store directly.
    float* yb = y + ((size_t)(b * 16 + 4 * r) * Ln) + l0;
    #pragma unroll
    for (int o = 0; o < 4; o++) {
        float* row = yb + (size_t)o * Ln;
        ulonglong2 s0; s0.x = acc[o][0]; s0.y = acc[o][1];
        ulonglong2 s1; s1.x = acc[o][2]; s1.y = acc[o][3];
        *(ulonglong2*)(row)     = s0;
        *(ulonglong2*)(row + 4) = s1;
    }
}

extern "C" void kernel_launch(void* const* d_in, const int* in_sizes, int n_in,
                              void* d_out, int out_size)
{
    const float* x  = (const float*)d_in[0];
    const float* k0 = (const float*)d_in[1];
    const float* k1 = (const float*)d_in[2];
    const float* k2 = (const float*)d_in[3];
    const float* k3 = (const float*)d_in[4];
    float* y = (float*)d_out;

    // Stage 1 (single staging node): pack weights directly into the constant
    // bank's backing store. cudaGetSymbolAddress is a host-side query.
    void* cdst = nullptr;
    cudaGetSymbolAddress(&cdst, cWd);
    pack_weights_kernel<<<1, 640>>>(k0, k1, k2, k3, (u64*)cdst);

    // Stage 2: the conv. 8 positions/thread, 256 threads/block.
    dim3 grid(Ln / 2048, 4, 32);  // (pos tiles, relation, batch)
    dim3 block(256);
    conv4x8x5_kernel<<<grid, block>>>(x, y);
}